// round 1
// baseline (speedup 1.0000x reference)
#include <cuda_runtime.h>

// ---------------------------------------------------------------------------
// Problem: out = emb[ids_en] + (S @ V) where
//   proj = emb @ Qdense                      [300,512]   (vocab-level, tiny)
//   G    = proj @ proj^T                     [300,300]   (Gram table)
//   V[b] = proj[ids_fr[b,:]]                 [64,512]    (gather)
//   S[b,q,k] = G[t_q,t_k] * (t_k != 0)       [64,64]     (gather + mask)
//   encoded[b] = S[b] @ V[b]                 [64,512]
// Exploits |vocab|=300 to collapse the 34 GF qkv GEMM and the 4.3 GF score
// computation into two tiny precomputes + gathers. Remaining GEMM done with
// packed fp32x2 FMA.
// ---------------------------------------------------------------------------

namespace {
constexpr int kB = 1024;
constexpr int kS = 64;
constexpr int kV = 300;
constexpr int kD = 512;
constexpr int VS_STRIDE = 516;  // 64x512 V tile, +4 float pad (bank spread, 16B aligned)
constexpr int SMEM_MAIN = kS * VS_STRIDE * 4   // V tile fp32
                        + kS * kS * 8          // S duplicated-packed f32x2
                        + 2 * kS * 4;          // token id arrays
}

__device__ float g_proj[kV * kD];   // 600 KB scratch (static device array: no allocs)
__device__ float g_gram[kV * kV];   // 360 KB scratch

// packed fp32x2 FMA: d = a * b + d   (sm_100+ PTX)
#define FMA2(d, a, b) asm("fma.rn.f32x2 %0, %1, %2, %0;" : "+l"(d) : "l"(a), "l"(b))

__device__ __forceinline__ float2 u2f2(unsigned long long u) {
    float2 f;
    asm("mov.b64 {%0, %1}, %2;" : "=f"(f.x), "=f"(f.y) : "l"(u));
    return f;
}

// ---------------------------------------------------------------------------
// Kernel 1: proj[300,512] = emb[300,512] @ Qdense[512,512]   (~0.16 GF)
// grid (19,4): 16-row x 128-col tiles. A staged in smem, B via L1 (__ldg).
// ---------------------------------------------------------------------------
__global__ void __launch_bounds__(256) proj_kernel(const float* __restrict__ emb,
                                                   const float* __restrict__ Wq) {
    __shared__ float As[16 * VS_STRIDE];  // 16 rows x 512 cols, pad stride
    int r0 = blockIdx.x * 16, c0 = blockIdx.y * 128;
    for (int idx = threadIdx.x; idx < 16 * 128; idx += 256) {
        int r = idx >> 7, c4 = idx & 127;
        float4 v = make_float4(0.f, 0.f, 0.f, 0.f);
        if (r0 + r < kV) v = *(const float4*)(emb + (r0 + r) * kD + c4 * 4);
        *(float4*)(As + r * VS_STRIDE + c4 * 4) = v;
    }
    __syncthreads();
    int ti = threadIdx.x & 15;          // row within tile
    int tc = threadIdx.x >> 4;          // col group (8 cols)
    int c = c0 + tc * 8;
    float acc[8] = {0.f, 0.f, 0.f, 0.f, 0.f, 0.f, 0.f, 0.f};
#pragma unroll 4
    for (int k = 0; k < kD; k++) {
        float a = As[ti * VS_STRIDE + k];
        float4 b0 = __ldg((const float4*)(Wq + k * kD + c));
        float4 b1 = __ldg((const float4*)(Wq + k * kD + c + 4));
        acc[0] += a * b0.x; acc[1] += a * b0.y; acc[2] += a * b0.z; acc[3] += a * b0.w;
        acc[4] += a * b1.x; acc[5] += a * b1.y; acc[6] += a * b1.z; acc[7] += a * b1.w;
    }
    int r = r0 + ti;
    if (r < kV) {
        float* o = g_proj + r * kD + c;
        *(float4*)o       = make_float4(acc[0], acc[1], acc[2], acc[3]);
        *(float4*)(o + 4) = make_float4(acc[4], acc[5], acc[6], acc[7]);
    }
}

// ---------------------------------------------------------------------------
// Kernel 2: G[300,300] = proj @ proj^T   (~0.09 GF)
// grid (19,19): 16x16 output tiles, K chunked by 128 through smem.
// ---------------------------------------------------------------------------
__global__ void __launch_bounds__(256) gram_kernel() {
    __shared__ float As[16 * 132];
    __shared__ float Bs[16 * 132];
    int i0 = blockIdx.x * 16, j0 = blockIdx.y * 16;
    int ti = threadIdx.x & 15, tj = threadIdx.x >> 4;
    float acc = 0.f;
    for (int kc = 0; kc < kD; kc += 128) {
        __syncthreads();
        for (int idx = threadIdx.x; idx < 2 * 16 * 32; idx += 256) {
            int t = idx >> 9;                       // 0 = A tile, 1 = B tile
            int r = (idx >> 5) & 15, c4 = idx & 31;
            int row = (t ? j0 : i0) + r;
            float4 v = make_float4(0.f, 0.f, 0.f, 0.f);
            if (row < kV) v = *(const float4*)(g_proj + row * kD + kc + c4 * 4);
            float* dst = t ? Bs : As;
            *(float4*)(dst + r * 132 + c4 * 4) = v;
        }
        __syncthreads();
#pragma unroll 8
        for (int k = 0; k < 128; k++)
            acc += As[ti * 132 + k] * Bs[tj * 132 + k];
    }
    int i = i0 + ti, j = j0 + tj;
    if (i < kV && j < kV) g_gram[i * kV + j] = acc;
}

// ---------------------------------------------------------------------------
// Kernel 3 (main): one CTA per batch.
//   gather V = proj[ids_fr] into smem (64x512 fp32, padded stride)
//   gather S from Gram table, masked, stored DUPLICATED-PACKED for f32x2 FMA
//   E = S @ V with fp32x2 packed FMA; out = E + emb[ids_en]
// Warp tiling: lane = (qi in [0,8), di in [0,4)), warp w owns 32-col slice.
// Each thread: 8q x 8d accumulators (32 x u64). No cross-warp V redundancy.
// ---------------------------------------------------------------------------
__global__ void __launch_bounds__(256, 1) main_kernel(
    const int* __restrict__ ids_en, const int* __restrict__ ids_fr,
    const float* __restrict__ emb, float* __restrict__ out) {
    extern __shared__ char smem[];
    float* Vs = (float*)smem;
    unsigned long long* S2 = (unsigned long long*)(smem + kS * VS_STRIDE * 4);
    int* tfr = (int*)(smem + kS * VS_STRIDE * 4 + kS * kS * 8);
    int* ten = tfr + kS;

    int b = blockIdx.x;
    int tid = threadIdx.x;
    if (tid < 64)       tfr[tid]      = ids_fr[b * 64 + tid];
    else if (tid < 128) ten[tid - 64] = ids_en[b * 64 + (tid - 64)];
    __syncthreads();

    // Gather V rows (proj is L2-resident: 600 KB)
    for (int idx = tid; idx < 64 * 128; idx += 256) {
        int r = idx >> 7, c4 = idx & 127;
        float4 v = __ldg((const float4*)(g_proj + tfr[r] * kD + c4 * 4));
        *(float4*)(Vs + r * VS_STRIDE + c4 * 4) = v;
    }
    // Build S, duplicated-packed: S2[q*64+k] = {s, s} as f32x2
    for (int idx = tid; idx < 64 * 64; idx += 256) {
        int q = idx >> 6, k = idx & 63;
        int tk = tfr[k];
        float s = (tk != 0) ? __ldg(g_gram + tfr[q] * kV + tk) : 0.f;
        unsigned long long p;
        asm("mov.b64 %0, {%1, %1};" : "=l"(p) : "f"(s));
        S2[q * 64 + k] = p;
    }
    __syncthreads();

    int lane = tid & 31, w = tid >> 5;
    int di = lane & 3, qi = lane >> 2;

    for (int pass = 0; pass < 2; pass++) {
        int cA = pass * 256 + w * 32 + di * 4;  // cols cA..cA+3
        int cB = cA + 16;                        // cols cB..cB+3
        unsigned long long aA[8][2], aB[8][2];
#pragma unroll
        for (int i = 0; i < 8; i++) {
            aA[i][0] = aA[i][1] = 0ull;
            aB[i][0] = aB[i][1] = 0ull;
        }
#pragma unroll 8
        for (int k = 0; k < 64; k += 2) {
            ulonglong2 vA0 = *(const ulonglong2*)(Vs + k * VS_STRIDE + cA);
            ulonglong2 vB0 = *(const ulonglong2*)(Vs + k * VS_STRIDE + cB);
            ulonglong2 vA1 = *(const ulonglong2*)(Vs + (k + 1) * VS_STRIDE + cA);
            ulonglong2 vB1 = *(const ulonglong2*)(Vs + (k + 1) * VS_STRIDE + cB);
#pragma unroll
            for (int i = 0; i < 8; i++) {
                ulonglong2 s = *(const ulonglong2*)(S2 + (qi * 8 + i) * 64 + k);
                FMA2(aA[i][0], s.x, vA0.x);
                FMA2(aA[i][1], s.x, vA0.y);
                FMA2(aB[i][0], s.x, vB0.x);
                FMA2(aB[i][1], s.x, vB0.y);
                FMA2(aA[i][0], s.y, vA1.x);
                FMA2(aA[i][1], s.y, vA1.y);
                FMA2(aB[i][0], s.y, vB1.x);
                FMA2(aB[i][1], s.y, vB1.y);
            }
        }
        // Epilogue: add gathered emb[ids_en] rows, store fp32
#pragma unroll
        for (int i = 0; i < 8; i++) {
            int q = qi * 8 + i;
            const float* er = emb + ten[q] * kD;
            float4 eA = __ldg((const float4*)(er + cA));
            float4 eB = __ldg((const float4*)(er + cB));
            float2 a0 = u2f2(aA[i][0]), a1 = u2f2(aA[i][1]);
            float2 b0 = u2f2(aB[i][0]), b1 = u2f2(aB[i][1]);
            float* op = out + ((long)b * 64 + q) * kD;
            *(float4*)(op + cA) = make_float4(a0.x + eA.x, a0.y + eA.y,
                                              a1.x + eA.z, a1.y + eA.w);
            *(float4*)(op + cB) = make_float4(b0.x + eB.x, b0.y + eB.y,
                                              b1.x + eB.z, b1.y + eB.w);
        }
    }
}

// ---------------------------------------------------------------------------
extern "C" void kernel_launch(void* const* d_in, const int* in_sizes, int n_in,
                              void* d_out, int out_size) {
    (void)in_sizes; (void)n_in; (void)out_size;
    const int* ids_en  = (const int*)d_in[0];
    const int* ids_fr  = (const int*)d_in[1];
    const float* emb   = (const float*)d_in[2];
    const float* Wq    = (const float*)d_in[3];
    float* out         = (float*)d_out;

    proj_kernel<<<dim3(19, 4), 256>>>(emb, Wq);
    gram_kernel<<<dim3(19, 19), 256>>>();
    cudaFuncSetAttribute(main_kernel, cudaFuncAttributeMaxDynamicSharedMemorySize,
                         SMEM_MAIN);
    main_kernel<<<kB, 256, SMEM_MAIN>>>(ids_en, ids_fr, emb, out);
}

// round 2
// speedup vs baseline: 1.4103x; 1.4103x over previous
#include <cuda_runtime.h>

// ---------------------------------------------------------------------------
// out = emb[ids_en] + S @ V  with
//   proj = emb @ Qdense [300,512], G = proj projT [300,300]  (vocab precompute)
//   V[b] = proj[ids_fr[b]], S[b,q,k] = G[tq,tk]*(tk!=0), enc = S@V
// ---------------------------------------------------------------------------

namespace {
constexpr int kB = 1024;
constexpr int kS = 64;
constexpr int kV = 300;
constexpr int kD = 512;
constexpr int VS_STRIDE = 516;  // V tile row stride (floats), 16B-aligned, bank-spread
constexpr int SMEM_MAIN = kS * VS_STRIDE * 4 + kS * kS * 8 + 2 * kS * 4;
}

__device__ float g_proj[kV * kD];   // 600 KB scratch
__device__ float g_gram[kV * kV];   // 360 KB scratch

#define FMA2(d, a, b) asm("fma.rn.f32x2 %0, %1, %2, %0;" : "+l"(d) : "l"(a), "l"(b))

__device__ __forceinline__ float2 u2f2(unsigned long long u) {
    float2 f;
    asm("mov.b64 {%0, %1}, %2;" : "=f"(f.x), "=f"(f.y) : "l"(u));
    return f;
}

// ---------------------------------------------------------------------------
// Kernel 1: proj = emb @ Qdense. grid (19,8): 16-row x 64-col tiles, 152 CTAs.
// K chunked by 64 through smem; 4 outputs/thread.
// ---------------------------------------------------------------------------
__global__ void __launch_bounds__(256) proj_kernel(const float* __restrict__ emb,
                                                   const float* __restrict__ Wq) {
    __shared__ float As[16 * 65];   // [r][k] stride 65 -> conflict-free a reads
    __shared__ float Bs[64 * 68];   // [k][c] stride 68 -> aligned float4 reads
    const int r0 = blockIdx.x * 16, c0 = blockIdx.y * 64;
    const int t = threadIdx.x;
    const int r = t & 15, cg = t >> 4;         // compute mapping: row r, cols cg*4..+3
    float4 acc = make_float4(0.f, 0.f, 0.f, 0.f);

    for (int kc = 0; kc < kD; kc += 64) {
        __syncthreads();
        {   // stage A chunk: 16 rows x 64 k  (1 float4 per thread)
            int ar = t >> 4, ak4 = t & 15;
            float4 v = make_float4(0.f, 0.f, 0.f, 0.f);
            if (r0 + ar < kV) v = *(const float4*)(emb + (r0 + ar) * kD + kc + ak4 * 4);
            float* d = As + ar * 65 + ak4 * 4;
            d[0] = v.x; d[1] = v.y; d[2] = v.z; d[3] = v.w;
        }
        {   // stage B chunk: 64 k x 64 cols (4 float4 per thread)
            int bc4 = t & 15;
#pragma unroll
            for (int j = 0; j < 4; j++) {
                int bk = (t >> 4) + 16 * j;
                float4 v = *(const float4*)(Wq + (kc + bk) * kD + c0 + bc4 * 4);
                *(float4*)(Bs + bk * 68 + bc4 * 4) = v;
            }
        }
        __syncthreads();
#pragma unroll 8
        for (int kk = 0; kk < 64; kk++) {
            float a = As[r * 65 + kk];
            float4 bv = *(const float4*)(Bs + kk * 68 + cg * 4);
            acc.x = fmaf(a, bv.x, acc.x);
            acc.y = fmaf(a, bv.y, acc.y);
            acc.z = fmaf(a, bv.z, acc.z);
            acc.w = fmaf(a, bv.w, acc.w);
        }
    }
    if (r0 + r < kV)
        *(float4*)(g_proj + (r0 + r) * kD + c0 + cg * 4) = acc;
}

// ---------------------------------------------------------------------------
// Kernel 2: G = proj @ projT. grid (10,10): 32x32 tiles, 2x2 outputs/thread,
// K chunked by 128 through smem, float2 k-reads.
// ---------------------------------------------------------------------------
__global__ void __launch_bounds__(256) gram_kernel() {
    __shared__ float As[32 * 130];  // [i][k] stride 130 (float2-aligned, spread)
    __shared__ float Bs[32 * 130];
    const int i0 = blockIdx.x * 32, j0 = blockIdx.y * 32;
    const int t = threadIdx.x;
    const int tx = t & 15, ty = t >> 4;
    float a00 = 0.f, a01 = 0.f, a10 = 0.f, a11 = 0.f;

    for (int kc = 0; kc < kD; kc += 128) {
        __syncthreads();
        {   // stage both 32x128 chunks (4 float4 loads each, float2 stores)
            int sr = t >> 3;                 // 0..31
#pragma unroll
            for (int j = 0; j < 4; j++) {
                int c4 = (t & 7) + 8 * j;    // 0..31 float4 cols
                float4 va = make_float4(0.f, 0.f, 0.f, 0.f);
                float4 vb = make_float4(0.f, 0.f, 0.f, 0.f);
                if (i0 + sr < kV) va = *(const float4*)(g_proj + (i0 + sr) * kD + kc + c4 * 4);
                if (j0 + sr < kV) vb = *(const float4*)(g_proj + (j0 + sr) * kD + kc + c4 * 4);
                float2* da = (float2*)(As + sr * 130 + c4 * 4);
                float2* db = (float2*)(Bs + sr * 130 + c4 * 4);
                da[0] = make_float2(va.x, va.y); da[1] = make_float2(va.z, va.w);
                db[0] = make_float2(vb.x, vb.y); db[1] = make_float2(vb.z, vb.w);
            }
        }
        __syncthreads();
#pragma unroll 8
        for (int kk = 0; kk < 128; kk += 2) {
            float2 x0 = *(const float2*)(As + ty * 130 + kk);
            float2 x1 = *(const float2*)(As + (ty + 16) * 130 + kk);
            float2 y0 = *(const float2*)(Bs + tx * 130 + kk);
            float2 y1 = *(const float2*)(Bs + (tx + 16) * 130 + kk);
            a00 = fmaf(x0.x, y0.x, a00); a00 = fmaf(x0.y, y0.y, a00);
            a01 = fmaf(x0.x, y1.x, a01); a01 = fmaf(x0.y, y1.y, a01);
            a10 = fmaf(x1.x, y0.x, a10); a10 = fmaf(x1.y, y0.y, a10);
            a11 = fmaf(x1.x, y1.x, a11); a11 = fmaf(x1.y, y1.y, a11);
        }
    }
    int i = i0 + ty, j = j0 + tx;
    if (i < kV) {
        if (j < kV)      g_gram[i * kV + j] = a00;
        if (j + 16 < kV) g_gram[i * kV + j + 16] = a01;
    }
    if (i + 16 < kV) {
        if (j < kV)      g_gram[(i + 16) * kV + j] = a10;
        if (j + 16 < kV) g_gram[(i + 16) * kV + j + 16] = a11;
    }
}

// ---------------------------------------------------------------------------
// Kernel 3 (main): one CTA per batch, 512 threads (4 warps/SMSP).
// Per thread per pass: 4 q-rows x 8 cols -> 16 u64 accumulators, f32x2 FMA.
// k-loop unroll capped at 2 to keep regs ~110 (round-1 spilled at unroll 8).
// ---------------------------------------------------------------------------
__global__ void __launch_bounds__(512, 1) main_kernel(
    const int* __restrict__ ids_en, const int* __restrict__ ids_fr,
    const float* __restrict__ emb, float* __restrict__ out) {
    extern __shared__ char smem[];
    float* Vs = (float*)smem;
    unsigned long long* S2 = (unsigned long long*)(smem + kS * VS_STRIDE * 4);
    int* tfr = (int*)(smem + kS * VS_STRIDE * 4 + kS * kS * 8);
    int* ten = tfr + kS;

    const int b = blockIdx.x;
    const int tid = threadIdx.x;
    if (tid < 64)       tfr[tid]      = ids_fr[b * 64 + tid];
    else if (tid < 128) ten[tid - 64] = ids_en[b * 64 + (tid - 64)];
    __syncthreads();

    // Gather V rows from L2-resident proj (16 float4 per thread)
    for (int idx = tid; idx < 64 * 128; idx += 512) {
        int r = idx >> 7, c4 = idx & 127;
        float4 v = __ldg((const float4*)(g_proj + tfr[r] * kD + c4 * 4));
        *(float4*)(Vs + r * VS_STRIDE + c4 * 4) = v;
    }
    // Build S duplicated-packed: S2[q*64+k] = {s,s}
    for (int idx = tid; idx < 64 * 64; idx += 512) {
        int q = idx >> 6, k = idx & 63;
        int tk = tfr[k];
        float s = (tk != 0) ? __ldg(g_gram + tfr[q] * kV + tk) : 0.f;
        unsigned long long p;
        asm("mov.b64 %0, {%1, %1};" : "=l"(p) : "f"(s));
        S2[q * 64 + k] = p;
    }
    __syncthreads();

    const int lane = tid & 31, w = tid >> 5;
    const int di = lane & 3, qi = lane >> 2;
    const int qq = (w >> 3) * 32 + qi * 4;        // 4 q-rows qq..qq+3
    const int cbase = (w & 7) * 32 + di * 4;

    for (int pass = 0; pass < 2; pass++) {
        const int cA = pass * 256 + cbase;
        const int cB = cA + 16;
        unsigned long long aA[4][2], aB[4][2];
#pragma unroll
        for (int i = 0; i < 4; i++) {
            aA[i][0] = aA[i][1] = 0ull;
            aB[i][0] = aB[i][1] = 0ull;
        }
#pragma unroll 2
        for (int k = 0; k < 64; k += 2) {
            ulonglong2 vA0 = *(const ulonglong2*)(Vs + k * VS_STRIDE + cA);
            ulonglong2 vB0 = *(const ulonglong2*)(Vs + k * VS_STRIDE + cB);
            ulonglong2 vA1 = *(const ulonglong2*)(Vs + (k + 1) * VS_STRIDE + cA);
            ulonglong2 vB1 = *(const ulonglong2*)(Vs + (k + 1) * VS_STRIDE + cB);
#pragma unroll
            for (int i = 0; i < 4; i++) {
                ulonglong2 s = *(const ulonglong2*)(S2 + (qq + i) * 64 + k);
                FMA2(aA[i][0], s.x, vA0.x);
                FMA2(aA[i][1], s.x, vA0.y);
                FMA2(aB[i][0], s.x, vB0.x);
                FMA2(aB[i][1], s.x, vB0.y);
                FMA2(aA[i][0], s.y, vA1.x);
                FMA2(aA[i][1], s.y, vA1.y);
                FMA2(aB[i][0], s.y, vB1.x);
                FMA2(aB[i][1], s.y, vB1.y);
            }
        }
#pragma unroll
        for (int i = 0; i < 4; i++) {
            int q = qq + i;
            const float* er = emb + ten[q] * kD;
            float4 eA = __ldg((const float4*)(er + cA));
            float4 eB = __ldg((const float4*)(er + cB));
            float2 a0 = u2f2(aA[i][0]), a1 = u2f2(aA[i][1]);
            float2 b0 = u2f2(aB[i][0]), b1 = u2f2(aB[i][1]);
            float* op = out + ((long)b * 64 + q) * kD;
            *(float4*)(op + cA) = make_float4(a0.x + eA.x, a0.y + eA.y,
                                              a1.x + eA.z, a1.y + eA.w);
            *(float4*)(op + cB) = make_float4(b0.x + eB.x, b0.y + eB.y,
                                              b1.x + eB.z, b1.y + eB.w);
        }
    }
}

// ---------------------------------------------------------------------------
extern "C" void kernel_launch(void* const* d_in, const int* in_sizes, int n_in,
                              void* d_out, int out_size) {
    (void)in_sizes; (void)n_in; (void)out_size;
    const int* ids_en = (const int*)d_in[0];
    const int* ids_fr = (const int*)d_in[1];
    const float* emb  = (const float*)d_in[2];
    const float* Wq   = (const float*)d_in[3];
    float* out        = (float*)d_out;

    proj_kernel<<<dim3(19, 8), 256>>>(emb, Wq);
    gram_kernel<<<dim3(10, 10), 256>>>();
    cudaFuncSetAttribute(main_kernel, cudaFuncAttributeMaxDynamicSharedMemorySize,
                         SMEM_MAIN);
    main_kernel<<<kB, 512, SMEM_MAIN>>>(ids_en, ids_fr, emb, out);
}

// round 3
// speedup vs baseline: 1.9165x; 1.3589x over previous
#include <cuda_runtime.h>

// ---------------------------------------------------------------------------
// out = emb[ids_en] + S @ V  with
//   proj = emb @ Qdense [300,512], G = proj projT [300,300]  (vocab precompute)
//   V[b] = proj[ids_fr[b]], S[b,q,k] = G[tq,tk]*(tk!=0), enc = S@V
// ---------------------------------------------------------------------------

namespace {
constexpr int kB = 1024;
constexpr int kS = 64;
constexpr int kV = 300;
constexpr int kD = 512;
constexpr int kCH = 256;          // cols per main CTA (batch split in 2)
constexpr int VSTR = 260;         // V tile row stride (floats)
constexpr int SMEM_V   = kS * VSTR * 4;          // 66,560
constexpr int SMEM_S   = 32 * kS * 16;           // 32,768 (S2P)
constexpr int SMEM_MAIN = SMEM_V + SMEM_S + 2 * kS * 4;
}

__device__ float g_proj[kV * kD];   // 600 KB scratch
__device__ float g_gram[kV * kV];   // 360 KB scratch

#define FMA2(d, a, b) asm("fma.rn.f32x2 %0, %1, %2, %0;" : "+l"(d) : "l"(a), "l"(b))

__device__ __forceinline__ float2 u2f2(unsigned long long u) {
    float2 f;
    asm("mov.b64 {%0, %1}, %2;" : "=f"(f.x), "=f"(f.y) : "l"(u));
    return f;
}

// ---------------------------------------------------------------------------
// Kernel 1: proj = emb @ Qdense. grid (19,16): 16-row x 32-col tiles, 304 CTAs.
// K chunked by 64; conflict-free smem strides; 2 outputs/thread.
// ---------------------------------------------------------------------------
__global__ void __launch_bounds__(256) proj_kernel(const float* __restrict__ emb,
                                                   const float* __restrict__ Wq) {
    __shared__ float As[16 * 65];   // [r][k] stride 65: (r+kk)%32 -> conflict-free
    __shared__ float Bs[64 * 36];   // [k][c] stride 36: float4-aligned
    const int r0 = blockIdx.x * 16, c0 = blockIdx.y * 32;
    const int t = threadIdx.x;
    const int r = t & 15, cg = t >> 4;          // output: row r, cols c0+cg*2..+1
    float2 acc = make_float2(0.f, 0.f);

    for (int kc = 0; kc < kD; kc += 64) {
        __syncthreads();
        {   // stage A: 16 rows x 64 k, one float4 per thread, scalar stores
            int ar = t >> 4, ak4 = t & 15;
            float4 v = make_float4(0.f, 0.f, 0.f, 0.f);
            if (r0 + ar < kV) v = *(const float4*)(emb + (r0 + ar) * kD + kc + ak4 * 4);
            float* d = As + ar * 65 + ak4 * 4;
            d[0] = v.x; d[1] = v.y; d[2] = v.z; d[3] = v.w;
        }
        {   // stage B: 64 k x 32 c, two float4 per thread
            int c4 = t & 7;
#pragma unroll
            for (int j = 0; j < 2; j++) {
                int bk = (t >> 3) + 32 * j;
                float4 v = *(const float4*)(Wq + (kc + bk) * kD + c0 + c4 * 4);
                *(float4*)(Bs + bk * 36 + c4 * 4) = v;
            }
        }
        __syncthreads();
#pragma unroll 8
        for (int kk = 0; kk < 64; kk++) {
            float a = As[r * 65 + kk];
            float2 bv = *(const float2*)(Bs + kk * 36 + cg * 2);
            acc.x = fmaf(a, bv.x, acc.x);
            acc.y = fmaf(a, bv.y, acc.y);
        }
    }
    if (r0 + r < kV)
        *(float2*)(g_proj + (r0 + r) * kD + c0 + cg * 2) = acc;
}

// ---------------------------------------------------------------------------
// Kernel 2: G = proj @ projT. grid (10,10): 32x32 tiles, 2x2 outputs/thread.
// ---------------------------------------------------------------------------
__global__ void __launch_bounds__(256) gram_kernel() {
    __shared__ float As[32 * 130];
    __shared__ float Bs[32 * 130];
    const int i0 = blockIdx.x * 32, j0 = blockIdx.y * 32;
    const int t = threadIdx.x;
    const int tx = t & 15, ty = t >> 4;
    float a00 = 0.f, a01 = 0.f, a10 = 0.f, a11 = 0.f;

    for (int kc = 0; kc < kD; kc += 128) {
        __syncthreads();
        {
            int sr = t >> 3;
#pragma unroll
            for (int j = 0; j < 4; j++) {
                int c4 = (t & 7) + 8 * j;
                float4 va = make_float4(0.f, 0.f, 0.f, 0.f);
                float4 vb = make_float4(0.f, 0.f, 0.f, 0.f);
                if (i0 + sr < kV) va = *(const float4*)(g_proj + (i0 + sr) * kD + kc + c4 * 4);
                if (j0 + sr < kV) vb = *(const float4*)(g_proj + (j0 + sr) * kD + kc + c4 * 4);
                float2* da = (float2*)(As + sr * 130 + c4 * 4);
                float2* db = (float2*)(Bs + sr * 130 + c4 * 4);
                da[0] = make_float2(va.x, va.y); da[1] = make_float2(va.z, va.w);
                db[0] = make_float2(vb.x, vb.y); db[1] = make_float2(vb.z, vb.w);
            }
        }
        __syncthreads();
#pragma unroll 8
        for (int kk = 0; kk < 128; kk += 2) {
            float2 x0 = *(const float2*)(As + ty * 130 + kk);
            float2 x1 = *(const float2*)(As + (ty + 16) * 130 + kk);
            float2 y0 = *(const float2*)(Bs + tx * 130 + kk);
            float2 y1 = *(const float2*)(Bs + (tx + 16) * 130 + kk);
            a00 = fmaf(x0.x, y0.x, a00); a00 = fmaf(x0.y, y0.y, a00);
            a01 = fmaf(x0.x, y1.x, a01); a01 = fmaf(x0.y, y1.y, a01);
            a10 = fmaf(x1.x, y0.x, a10); a10 = fmaf(x1.y, y0.y, a10);
            a11 = fmaf(x1.x, y1.x, a11); a11 = fmaf(x1.y, y1.y, a11);
        }
    }
    int i = i0 + ty, j = j0 + tx;
    if (i < kV) {
        if (j < kV)      g_gram[i * kV + j] = a00;
        if (j + 16 < kV) g_gram[i * kV + j + 16] = a01;
    }
    if (i + 16 < kV) {
        if (j < kV)      g_gram[(i + 16) * kV + j] = a10;
        if (j + 16 < kV) g_gram[(i + 16) * kV + j + 16] = a11;
    }
}

// ---------------------------------------------------------------------------
// Kernel 3 (main): grid (1024, 2) -> CTA = (batch, 256-col half), 256 threads,
// ~97.5 KB smem -> 2 CTAs/SM. Conflict-free transposed k-pair-packed S:
//   S2P[kp][q] = ulonglong2{ {s_2kp, s_2kp}, {s_2kp+1, s_2kp+1} }
// Thread (qi,di) of warp w: q rows {8i+qi}, cols w*32 + di*4 (+16).
// S loads: 8 lanes 16B-contiguous -> 1 wavefront, broadcast x4. FMA2-bound.
// ---------------------------------------------------------------------------
__global__ void __launch_bounds__(256, 2) main_kernel(
    const int* __restrict__ ids_en, const int* __restrict__ ids_fr,
    const float* __restrict__ emb, float* __restrict__ out) {
    extern __shared__ char smem[];
    float* Vs = (float*)smem;
    ulonglong2* S2P = (ulonglong2*)(smem + SMEM_V);
    int* tfr = (int*)(smem + SMEM_V + SMEM_S);
    int* ten = tfr + kS;

    const int b = blockIdx.x;
    const int coff = blockIdx.y * kCH;
    const int tid = threadIdx.x;
    if (tid < 64)       tfr[tid]      = ids_fr[b * 64 + tid];
    else if (tid < 128) ten[tid - 64] = ids_en[b * 64 + (tid - 64)];
    __syncthreads();

    // Gather V rows (this CTA's 256-col slice) from L2-resident proj
    for (int idx = tid; idx < 64 * 64; idx += 256) {
        int r = idx >> 6, c4 = idx & 63;
        float4 v = __ldg((const float4*)(g_proj + tfr[r] * kD + coff + c4 * 4));
        *(float4*)(Vs + r * VSTR + c4 * 4) = v;
    }
    // Build S (transposed, k-pair packed, duplicated halves)
    for (int idx = tid; idx < 64 * 64; idx += 256) {
        int q = idx & 63, k = idx >> 6;
        int tk = tfr[k];
        float s = (tk != 0) ? __ldg(g_gram + tfr[q] * kV + tk) : 0.f;
        unsigned long long p;
        asm("mov.b64 %0, {%1, %1};" : "=l"(p) : "f"(s));
        ((unsigned long long*)S2P)[((k >> 1) * 64 + q) * 2 + (k & 1)] = p;
    }
    __syncthreads();

    const int lane = tid & 31, w = tid >> 5;
    const int di = lane & 3, qi = lane >> 2;
    const int cA = w * 32 + di * 4;
    const int cB = cA + 16;

    unsigned long long aA[8][2], aB[8][2];
#pragma unroll
    for (int i = 0; i < 8; i++) {
        aA[i][0] = aA[i][1] = 0ull;
        aB[i][0] = aB[i][1] = 0ull;
    }

#pragma unroll 2
    for (int kp = 0; kp < 32; kp++) {
        const float* v0 = Vs + (2 * kp) * VSTR;
        const float* v1 = v0 + VSTR;
        ulonglong2 vA0 = *(const ulonglong2*)(v0 + cA);
        ulonglong2 vB0 = *(const ulonglong2*)(v0 + cB);
        ulonglong2 vA1 = *(const ulonglong2*)(v1 + cA);
        ulonglong2 vB1 = *(const ulonglong2*)(v1 + cB);
        const ulonglong2* srow = S2P + kp * 64 + qi;
#pragma unroll
        for (int i = 0; i < 8; i++) {
            ulonglong2 s = srow[i * 8];          // q = 8*i + qi
            FMA2(aA[i][0], s.x, vA0.x);
            FMA2(aA[i][1], s.x, vA0.y);
            FMA2(aB[i][0], s.x, vB0.x);
            FMA2(aB[i][1], s.x, vB0.y);
            FMA2(aA[i][0], s.y, vA1.x);
            FMA2(aA[i][1], s.y, vA1.y);
            FMA2(aB[i][0], s.y, vB1.x);
            FMA2(aB[i][1], s.y, vB1.y);
        }
    }

    // Epilogue: add emb[ids_en] rows, store
#pragma unroll
    for (int i = 0; i < 8; i++) {
        int q = i * 8 + qi;
        const float* er = emb + ten[q] * kD + coff;
        float4 eA = __ldg((const float4*)(er + cA));
        float4 eB = __ldg((const float4*)(er + cB));
        float2 a0 = u2f2(aA[i][0]), a1 = u2f2(aA[i][1]);
        float2 b0 = u2f2(aB[i][0]), b1 = u2f2(aB[i][1]);
        float* op = out + ((long)b * 64 + q) * kD + coff;
        *(float4*)(op + cA) = make_float4(a0.x + eA.x, a0.y + eA.y,
                                          a1.x + eA.z, a1.y + eA.w);
        *(float4*)(op + cB) = make_float4(b0.x + eB.x, b0.y + eB.y,
                                          b1.x + eB.z, b1.y + eB.w);
    }
}

// ---------------------------------------------------------------------------
extern "C" void kernel_launch(void* const* d_in, const int* in_sizes, int n_in,
                              void* d_out, int out_size) {
    (void)in_sizes; (void)n_in; (void)out_size;
    const int* ids_en = (const int*)d_in[0];
    const int* ids_fr = (const int*)d_in[1];
    const float* emb  = (const float*)d_in[2];
    const float* Wq   = (const float*)d_in[3];
    float* out        = (float*)d_out;

    proj_kernel<<<dim3(19, 16), 256>>>(emb, Wq);
    gram_kernel<<<dim3(10, 10), 256>>>();
    cudaFuncSetAttribute(main_kernel, cudaFuncAttributeMaxDynamicSharedMemorySize,
                         SMEM_MAIN);
    main_kernel<<<dim3(kB, 2), 256, SMEM_MAIN>>>(ids_en, ids_fr, emb, out);
}

// round 5
// speedup vs baseline: 2.5001x; 1.3045x over previous
#include <cuda_runtime.h>
#include <cuda_bf16.h>
#include <cstdint>

// ---------------------------------------------------------------------------
// out = emb[ids_en] + S @ V with vocab-collapse precomputes:
//   proj = emb @ Qdense [300,512]  ->  G = proj projT [300,300]
//   V[b]=proj[ids_fr[b]], S[b,q,k]=G[tq,tk]*(tk!=0), enc = S@V
// enc computed with mma.sync bf16 3-product error-compensated split
// (S_hi*V_hi + S_hi*V_lo + S_lo*V_hi, fp32 accumulate). NOTE: tcgen05 is NOT
// available (harness builds through plain compute_103 PTX target).
// ---------------------------------------------------------------------------

namespace {
constexpr int kB = 1024;
constexpr int kV = 300;
constexpr int kD = 512;
constexpr int kN = 256;                  // cols per main CTA (batch split in 2)
constexpr int AST = 144;                 // A tile row stride bytes (64 bf16 + pad)
constexpr int BST = 144;                 // B tile row stride bytes

constexpr int OFF_TFR = 0;               // 64 int
constexpr int OFF_TEN = 256;             // 64 int
constexpr int OFF_AHI = 512;                     // S_hi [64 q][64 k] bf16
constexpr int OFF_ALO = OFF_AHI + 64 * AST;      // 9728
constexpr int OFF_BHI = OFF_ALO + 64 * AST;      // 18944: V^T hi [256 n][64 k]
constexpr int OFF_BLO = OFF_BHI + 256 * BST;     // 55808
constexpr int SMEM_MAIN = OFF_BLO + 256 * BST;   // 92672 B -> 2 CTAs/SM
}

__device__ float g_proj[kV * kD];   // 600 KB scratch
__device__ float g_gram[kV * kV];   // 360 KB scratch

// ---------------- helpers --------------------------------------------------
__device__ __forceinline__ uint32_t smem_u32(const void* p) {
    uint32_t a;
    asm("{ .reg .u64 t; cvta.to.shared.u64 t, %1; cvt.u32.u64 %0, t; }"
        : "=r"(a) : "l"(p));
    return a;
}
__device__ __forceinline__ void ldsm4(uint32_t* r, uint32_t addr) {
    asm volatile("ldmatrix.sync.aligned.m8n8.x4.shared.b16 {%0,%1,%2,%3}, [%4];"
                 : "=r"(r[0]), "=r"(r[1]), "=r"(r[2]), "=r"(r[3]) : "r"(addr));
}
__device__ __forceinline__ void ldsm2(uint32_t* r, uint32_t addr) {
    asm volatile("ldmatrix.sync.aligned.m8n8.x2.shared.b16 {%0,%1}, [%2];"
                 : "=r"(r[0]), "=r"(r[1]) : "r"(addr));
}
__device__ __forceinline__ void mma_bf16(float* c, const uint32_t* a,
                                         const uint32_t* b) {
    asm volatile(
        "mma.sync.aligned.m16n8k16.row.col.f32.bf16.bf16.f32 "
        "{%0,%1,%2,%3}, {%4,%5,%6,%7}, {%8,%9}, {%0,%1,%2,%3};"
        : "+f"(c[0]), "+f"(c[1]), "+f"(c[2]), "+f"(c[3])
        : "r"(a[0]), "r"(a[1]), "r"(a[2]), "r"(a[3]), "r"(b[0]), "r"(b[1]));
}
// split (f0, f1) fp32 -> packed bf16x2 hi + residual lo (f0 in low half)
__device__ __forceinline__ void split2(float f0, float f1, uint32_t& hi,
                                       uint32_t& lo) {
    asm("cvt.rn.bf16x2.f32 %0, %1, %2;" : "=r"(hi) : "f"(f1), "f"(f0));
    float h0 = __uint_as_float(hi << 16);
    float h1 = __uint_as_float(hi & 0xFFFF0000u);
    float r0 = f0 - h0, r1 = f1 - h1;
    asm("cvt.rn.bf16x2.f32 %0, %1, %2;" : "=r"(lo) : "f"(r1), "f"(r0));
}

// ---------------------------------------------------------------------------
// Kernel 1: proj = emb @ Qdense (unchanged)
// ---------------------------------------------------------------------------
__global__ void __launch_bounds__(256) proj_kernel(const float* __restrict__ emb,
                                                   const float* __restrict__ Wq) {
    __shared__ float As[16 * 65];
    __shared__ float Bs[64 * 36];
    const int r0 = blockIdx.x * 16, c0 = blockIdx.y * 32;
    const int t = threadIdx.x;
    const int r = t & 15, cg = t >> 4;
    float2 acc = make_float2(0.f, 0.f);

    for (int kc = 0; kc < kD; kc += 64) {
        __syncthreads();
        {
            int ar = t >> 4, ak4 = t & 15;
            float4 v = make_float4(0.f, 0.f, 0.f, 0.f);
            if (r0 + ar < kV) v = *(const float4*)(emb + (r0 + ar) * kD + kc + ak4 * 4);
            float* d = As + ar * 65 + ak4 * 4;
            d[0] = v.x; d[1] = v.y; d[2] = v.z; d[3] = v.w;
        }
        {
            int c4 = t & 7;
#pragma unroll
            for (int j = 0; j < 2; j++) {
                int bk = (t >> 3) + 32 * j;
                float4 v = *(const float4*)(Wq + (kc + bk) * kD + c0 + c4 * 4);
                *(float4*)(Bs + bk * 36 + c4 * 4) = v;
            }
        }
        __syncthreads();
#pragma unroll 8
        for (int kk = 0; kk < 64; kk++) {
            float a = As[r * 65 + kk];
            float2 bv = *(const float2*)(Bs + kk * 36 + cg * 2);
            acc.x = fmaf(a, bv.x, acc.x);
            acc.y = fmaf(a, bv.y, acc.y);
        }
    }
    if (r0 + r < kV)
        *(float2*)(g_proj + (r0 + r) * kD + c0 + cg * 2) = acc;
}

// ---------------------------------------------------------------------------
// Kernel 2: G = proj @ projT (unchanged)
// ---------------------------------------------------------------------------
__global__ void __launch_bounds__(256) gram_kernel() {
    __shared__ float As[32 * 130];
    __shared__ float Bs[32 * 130];
    const int i0 = blockIdx.x * 32, j0 = blockIdx.y * 32;
    const int t = threadIdx.x;
    const int tx = t & 15, ty = t >> 4;
    float a00 = 0.f, a01 = 0.f, a10 = 0.f, a11 = 0.f;

    for (int kc = 0; kc < kD; kc += 128) {
        __syncthreads();
        {
            int sr = t >> 3;
#pragma unroll
            for (int j = 0; j < 4; j++) {
                int c4 = (t & 7) + 8 * j;
                float4 va = make_float4(0.f, 0.f, 0.f, 0.f);
                float4 vb = make_float4(0.f, 0.f, 0.f, 0.f);
                if (i0 + sr < kV) va = *(const float4*)(g_proj + (i0 + sr) * kD + kc + c4 * 4);
                if (j0 + sr < kV) vb = *(const float4*)(g_proj + (j0 + sr) * kD + kc + c4 * 4);
                float2* da = (float2*)(As + sr * 130 + c4 * 4);
                float2* db = (float2*)(Bs + sr * 130 + c4 * 4);
                da[0] = make_float2(va.x, va.y); da[1] = make_float2(va.z, va.w);
                db[0] = make_float2(vb.x, vb.y); db[1] = make_float2(vb.z, vb.w);
            }
        }
        __syncthreads();
#pragma unroll 8
        for (int kk = 0; kk < 128; kk += 2) {
            float2 x0 = *(const float2*)(As + ty * 130 + kk);
            float2 x1 = *(const float2*)(As + (ty + 16) * 130 + kk);
            float2 y0 = *(const float2*)(Bs + tx * 130 + kk);
            float2 y1 = *(const float2*)(Bs + (tx + 16) * 130 + kk);
            a00 = fmaf(x0.x, y0.x, a00); a00 = fmaf(x0.y, y0.y, a00);
            a01 = fmaf(x0.x, y1.x, a01); a01 = fmaf(x0.y, y1.y, a01);
            a10 = fmaf(x1.x, y0.x, a10); a10 = fmaf(x1.y, y0.y, a10);
            a11 = fmaf(x1.x, y1.x, a11); a11 = fmaf(x1.y, y1.y, a11);
        }
    }
    int i = i0 + ty, j = j0 + tx;
    if (i < kV) {
        if (j < kV)      g_gram[i * kV + j] = a00;
        if (j + 16 < kV) g_gram[i * kV + j + 16] = a01;
    }
    if (i + 16 < kV) {
        if (j < kV)      g_gram[(i + 16) * kV + j] = a10;
        if (j + 16 < kV) g_gram[(i + 16) * kV + j + 16] = a11;
    }
}

// ---------------------------------------------------------------------------
// Kernel 3 (main, mma.sync bf16): grid (1024, 2); CTA = (batch, 256-col half),
// 256 threads, 92.7 KB smem -> 2 CTAs/SM.
// A = S split [64q][64k] bf16, row stride 144B.
// B = V^T split [256n][64k] bf16, row stride 144B (ldmatrix no-trans on [n][k]
// yields the col-major B fragment directly).
// Warp w: m-tile (w&3)*16 q-rows, n-half (w>>2)*128; 4 k-steps x 16 n-tiles x
// 3 products = 192 HMMA; fp32 acc in registers; epilogue adds emb gather.
// ---------------------------------------------------------------------------
__global__ void __launch_bounds__(256, 2) main_kernel(
    const int* __restrict__ ids_en, const int* __restrict__ ids_fr,
    const float* __restrict__ emb, float* __restrict__ out) {
    extern __shared__ char smem[];
    const uint32_t sb = smem_u32(smem);
    int* tfr = (int*)(smem + OFF_TFR);
    int* ten = (int*)(smem + OFF_TEN);

    const int b = blockIdx.x;
    const int coff = blockIdx.y * kN;
    const int tid = threadIdx.x;

    if (tid < 64)       tfr[tid]      = ids_fr[b * 64 + tid];
    else if (tid < 128) ten[tid - 64] = ids_en[b * 64 + (tid - 64)];
    __syncthreads();

    // ---- Fill B (V^T) tiles: task = (k-pair kp, 8-n block). Within a warp
    // kp = lane -> stores conflict-free; proj reads are 32B-sector aligned.
    for (int t4 = tid; t4 < 1024; t4 += 256) {
        int kp = t4 & 31, n0 = (t4 >> 5) * 8;
        const float* r0 = g_proj + (size_t)tfr[2 * kp] * kD + coff + n0;
        const float* r1 = g_proj + (size_t)tfr[2 * kp + 1] * kD + coff + n0;
        float4 a0 = __ldg((const float4*)r0), a1 = __ldg((const float4*)(r0 + 4));
        float4 b0 = __ldg((const float4*)r1), b1 = __ldg((const float4*)(r1 + 4));
        float fa[8] = {a0.x, a0.y, a0.z, a0.w, a1.x, a1.y, a1.z, a1.w};
        float fb[8] = {b0.x, b0.y, b0.z, b0.w, b1.x, b1.y, b1.z, b1.w};
#pragma unroll
        for (int i = 0; i < 8; i++) {
            uint32_t hi, lo;
            split2(fa[i], fb[i], hi, lo);  // (k even, k odd) pair
            uint32_t off = (uint32_t)((n0 + i) * BST + kp * 4);
            *(uint32_t*)(smem + OFF_BHI + off) = hi;
            *(uint32_t*)(smem + OFF_BLO + off) = lo;
        }
    }
    // ---- Fill A (S) tiles: task = (kp, q); masked Gram gather ---------------
    for (int t4 = tid; t4 < 2048; t4 += 256) {
        int kp = t4 & 31, q = t4 >> 5;
        int t0 = tfr[2 * kp], t1 = tfr[2 * kp + 1];
        const float* gr = g_gram + (size_t)tfr[q] * kV;
        float s0 = t0 ? __ldg(gr + t0) : 0.f;
        float s1 = t1 ? __ldg(gr + t1) : 0.f;
        uint32_t hi, lo;
        split2(s0, s1, hi, lo);
        uint32_t off = (uint32_t)(q * AST + kp * 4);
        *(uint32_t*)(smem + OFF_AHI + off) = hi;
        *(uint32_t*)(smem + OFF_ALO + off) = lo;
    }
    __syncthreads();

    // ---- MMA phase ----------------------------------------------------------
    const int lane = tid & 31, w = tid >> 5;
    const int q0 = (w & 3) * 16;
    const int nbase = (w >> 2) * 128;

    // ldmatrix lane address components
    const int arow = q0 + (lane & 7) + (lane & 8);
    const uint32_t aksel = ((lane >> 4) & 1) * 16;
    const uint32_t aHiBase = sb + OFF_AHI + (uint32_t)arow * AST + aksel;
    const uint32_t aLoBase = aHiBase + (OFF_ALO - OFF_AHI);
    const int brow = nbase + (lane & 7);
    const uint32_t bksel = ((lane >> 3) & 1) * 16;
    const uint32_t bHiBase = sb + OFF_BHI + (uint32_t)brow * BST + bksel;
    const uint32_t bLoBase = bHiBase + (OFF_BLO - OFF_BHI);

    float acc[16][4];
#pragma unroll
    for (int nt = 0; nt < 16; nt++)
#pragma unroll
        for (int i = 0; i < 4; i++) acc[nt][i] = 0.f;

#pragma unroll
    for (int kk = 0; kk < 4; kk++) {
        uint32_t ah[4], al[4];
        ldsm4(ah, aHiBase + kk * 32);
        ldsm4(al, aLoBase + kk * 32);
#pragma unroll
        for (int nt = 0; nt < 16; nt++) {
            uint32_t bh[2], bl[2];
            ldsm2(bh, bHiBase + (uint32_t)(nt * 8 * BST) + kk * 32);
            ldsm2(bl, bLoBase + (uint32_t)(nt * 8 * BST) + kk * 32);
            mma_bf16(acc[nt], ah, bh);
            mma_bf16(acc[nt], ah, bl);
            mma_bf16(acc[nt], al, bh);
        }
    }

    // ---- Epilogue: D element (q0 + l/4 [+8], nbase + nt*8 + 2(l%4) [+1]) ----
    const int row0 = q0 + (lane >> 2);
    const int row1 = row0 + 8;
    const int cl = 2 * (lane & 3);
    const float* e0 = emb + (size_t)ten[row0] * kD + coff + nbase + cl;
    const float* e1 = emb + (size_t)ten[row1] * kD + coff + nbase + cl;
    float* o0 = out + ((size_t)b * 64 + row0) * kD + coff + nbase + cl;
    float* o1 = out + ((size_t)b * 64 + row1) * kD + coff + nbase + cl;
#pragma unroll
    for (int nt = 0; nt < 16; nt++) {
        float2 g0 = __ldg((const float2*)(e0 + nt * 8));
        float2 g1 = __ldg((const float2*)(e1 + nt * 8));
        *(float2*)(o0 + nt * 8) = make_float2(acc[nt][0] + g0.x, acc[nt][1] + g0.y);
        *(float2*)(o1 + nt * 8) = make_float2(acc[nt][2] + g1.x, acc[nt][3] + g1.y);
    }
}

// ---------------------------------------------------------------------------
extern "C" void kernel_launch(void* const* d_in, const int* in_sizes, int n_in,
                              void* d_out, int out_size) {
    (void)in_sizes; (void)n_in; (void)out_size;
    const int* ids_en = (const int*)d_in[0];
    const int* ids_fr = (const int*)d_in[1];
    const float* emb  = (const float*)d_in[2];
    const float* Wq   = (const float*)d_in[3];
    float* out        = (float*)d_out;

    proj_kernel<<<dim3(19, 16), 256>>>(emb, Wq);
    gram_kernel<<<dim3(10, 10), 256>>>();
    cudaFuncSetAttribute(main_kernel, cudaFuncAttributeMaxDynamicSharedMemorySize,
                         SMEM_MAIN);
    main_kernel<<<dim3(kB, 2), 256, SMEM_MAIN>>>(ids_en, ids_fr, emb, out);
}

// round 6
// speedup vs baseline: 2.5353x; 1.0141x over previous
#include <cuda_runtime.h>
#include <cuda_bf16.h>
#include <cstdint>

// ---------------------------------------------------------------------------
// out = emb[ids_en] + S @ V with vocab-collapse precomputes:
//   proj = emb @ Qdense [300,512]  ->  G = proj projT [300,300]
//   V[b]=proj[ids_fr[b]], S[b,q,k]=G[tq,tk]*(tk!=0), enc = S@V
// enc via mma.sync bf16 3-product split (hi*hi + hi*lo + lo*hi, fp32 acc).
// bf16 hi/lo splits of proj and gram are PRECOMPUTED once per vocab entry and
// stored packed {hi16|lo16} -> main-kernel fills are gather + PRMT only.
// (tcgen05 unavailable: harness builds through plain compute_103 PTX.)
// ---------------------------------------------------------------------------

namespace {
constexpr int kB = 1024;
constexpr int kV = 300;
constexpr int kD = 512;
constexpr int kN = 128;                  // cols per main CTA (batch split in 4)
constexpr int AST = 144;                 // A tile row stride bytes (64 bf16 + pad)
constexpr int BST = 144;                 // B tile row stride bytes

constexpr int OFF_TFR = 0;               // 64 int
constexpr int OFF_TEN = 256;             // 64 int
constexpr int OFF_AHI = 512;                     // S_hi [64 q][64 k] bf16
constexpr int OFF_ALO = OFF_AHI + 64 * AST;      // 9728
constexpr int OFF_BHI = OFF_ALO + 64 * AST;      // 18944: V^T hi [128 n][64 k]
constexpr int OFF_BLO = OFF_BHI + kN * BST;      // 37376
constexpr int SMEM_MAIN = OFF_BLO + kN * BST;    // 55808 B -> 3 CTAs/SM
}

__device__ float    g_proj [kV * kD];    // fp32 proj (gram input)
__device__ uint32_t g_projs[kV * kD];    // packed {bf16 hi | bf16 lo} of proj
__device__ uint32_t g_grams[kV * kV];    // packed {bf16 hi | bf16 lo} of gram

// ---------------- helpers --------------------------------------------------
__device__ __forceinline__ uint32_t smem_u32(const void* p) {
    uint32_t a;
    asm("{ .reg .u64 t; cvta.to.shared.u64 t, %1; cvt.u32.u64 %0, t; }"
        : "=r"(a) : "l"(p));
    return a;
}
__device__ __forceinline__ uint32_t prmt(uint32_t a, uint32_t b, uint32_t sel) {
    uint32_t d;
    asm("prmt.b32 %0, %1, %2, %3;" : "=r"(d) : "r"(a), "r"(b), "r"(sel));
    return d;
}
__device__ __forceinline__ void ldsm4(uint32_t* r, uint32_t addr) {
    asm volatile("ldmatrix.sync.aligned.m8n8.x4.shared.b16 {%0,%1,%2,%3}, [%4];"
                 : "=r"(r[0]), "=r"(r[1]), "=r"(r[2]), "=r"(r[3]) : "r"(addr));
}
__device__ __forceinline__ void mma_bf16(float* c, const uint32_t* a,
                                         const uint32_t* b) {
    asm volatile(
        "mma.sync.aligned.m16n8k16.row.col.f32.bf16.bf16.f32 "
        "{%0,%1,%2,%3}, {%4,%5,%6,%7}, {%8,%9}, {%0,%1,%2,%3};"
        : "+f"(c[0]), "+f"(c[1]), "+f"(c[2]), "+f"(c[3])
        : "r"(a[0]), "r"(a[1]), "r"(a[2]), "r"(a[3]), "r"(b[0]), "r"(b[1]));
}
// fp32 -> packed {bf16 hi <<16 | bf16 residual-lo}
__device__ __forceinline__ uint32_t pack_split(float v) {
    __nv_bfloat16 h = __float2bfloat16(v);
    float hf = __bfloat162float(h);
    __nv_bfloat16 l = __float2bfloat16(v - hf);
    return ((uint32_t)__bfloat16_as_ushort(h) << 16) | __bfloat16_as_ushort(l);
}

// ---------------------------------------------------------------------------
// Kernel 1: proj = emb @ Qdense. grid (38,16): 8-row x 32-col tiles, 608 CTAs
// (4 CTAs/SM -> 2x occupancy vs 304). Writes fp32 g_proj + packed g_projs.
// ---------------------------------------------------------------------------
__global__ void __launch_bounds__(256) proj_kernel(const float* __restrict__ emb,
                                                   const float* __restrict__ Wq) {
    __shared__ float As[8 * 65];
    __shared__ float Bs[64 * 36];
    const int r0 = blockIdx.x * 8, c0 = blockIdx.y * 32;
    const int t = threadIdx.x;
    const int r = t >> 5, c = t & 31;    // 1 output/thread; warp = one row
    float acc = 0.f;

    for (int kc = 0; kc < kD; kc += 64) {
        __syncthreads();
        if (t < 128) {  // stage A: 8 rows x 64 k
            int ar = t >> 4, ak4 = t & 15;
            float4 v = make_float4(0.f, 0.f, 0.f, 0.f);
            if (r0 + ar < kV) v = *(const float4*)(emb + (r0 + ar) * kD + kc + ak4 * 4);
            float* d = As + ar * 65 + ak4 * 4;
            d[0] = v.x; d[1] = v.y; d[2] = v.z; d[3] = v.w;
        }
        {   // stage B: 64 k x 32 c
            int c4 = t & 7;
#pragma unroll
            for (int j = 0; j < 2; j++) {
                int bk = (t >> 3) + 32 * j;
                float4 v = *(const float4*)(Wq + (kc + bk) * kD + c0 + c4 * 4);
                *(float4*)(Bs + bk * 36 + c4 * 4) = v;
            }
        }
        __syncthreads();
#pragma unroll 16
        for (int kk = 0; kk < 64; kk++)
            acc = fmaf(As[r * 65 + kk], Bs[kk * 36 + c], acc);
    }
    if (r0 + r < kV) {
        int idx = (r0 + r) * kD + c0 + c;
        g_proj[idx] = acc;
        g_projs[idx] = pack_split(acc);
    }
}

// ---------------------------------------------------------------------------
// Kernel 2: G = proj @ projT; writes ONLY packed g_grams.
// ---------------------------------------------------------------------------
__global__ void __launch_bounds__(256) gram_kernel() {
    __shared__ float As[32 * 130];
    __shared__ float Bs[32 * 130];
    const int i0 = blockIdx.x * 32, j0 = blockIdx.y * 32;
    const int t = threadIdx.x;
    const int tx = t & 15, ty = t >> 4;
    float a00 = 0.f, a01 = 0.f, a10 = 0.f, a11 = 0.f;

    for (int kc = 0; kc < kD; kc += 128) {
        __syncthreads();
        {
            int sr = t >> 3;
#pragma unroll
            for (int j = 0; j < 4; j++) {
                int c4 = (t & 7) + 8 * j;
                float4 va = make_float4(0.f, 0.f, 0.f, 0.f);
                float4 vb = make_float4(0.f, 0.f, 0.f, 0.f);
                if (i0 + sr < kV) va = *(const float4*)(g_proj + (i0 + sr) * kD + kc + c4 * 4);
                if (j0 + sr < kV) vb = *(const float4*)(g_proj + (j0 + sr) * kD + kc + c4 * 4);
                float2* da = (float2*)(As + sr * 130 + c4 * 4);
                float2* db = (float2*)(Bs + sr * 130 + c4 * 4);
                da[0] = make_float2(va.x, va.y); da[1] = make_float2(va.z, va.w);
                db[0] = make_float2(vb.x, vb.y); db[1] = make_float2(vb.z, vb.w);
            }
        }
        __syncthreads();
#pragma unroll 8
        for (int kk = 0; kk < 128; kk += 2) {
            float2 x0 = *(const float2*)(As + ty * 130 + kk);
            float2 x1 = *(const float2*)(As + (ty + 16) * 130 + kk);
            float2 y0 = *(const float2*)(Bs + tx * 130 + kk);
            float2 y1 = *(const float2*)(Bs + (tx + 16) * 130 + kk);
            a00 = fmaf(x0.x, y0.x, a00); a00 = fmaf(x0.y, y0.y, a00);
            a01 = fmaf(x0.x, y1.x, a01); a01 = fmaf(x0.y, y1.y, a01);
            a10 = fmaf(x1.x, y0.x, a10); a10 = fmaf(x1.y, y0.y, a10);
            a11 = fmaf(x1.x, y1.x, a11); a11 = fmaf(x1.y, y1.y, a11);
        }
    }
    int i = i0 + ty, j = j0 + tx;
    if (i < kV) {
        if (j < kV)      g_grams[i * kV + j] = pack_split(a00);
        if (j + 16 < kV) g_grams[i * kV + j + 16] = pack_split(a01);
    }
    if (i + 16 < kV) {
        if (j < kV)      g_grams[(i + 16) * kV + j] = pack_split(a10);
        if (j + 16 < kV) g_grams[(i + 16) * kV + j + 16] = pack_split(a11);
    }
}

// ---------------------------------------------------------------------------
// Kernel 3 (main): grid (1024, 4); CTA = (batch, 128-col quarter), 256 thr,
// 55.8 KB smem, 3 CTAs/SM. Fills = packed gather + PRMT only.
// Warp w: m-tile (w&3)*16 q-rows, n-half (w>>2)*64; ldsm x4 everywhere;
// 4 kk x 4 ntile-pairs x 6 mma = 96 HMMA/warp.
// ---------------------------------------------------------------------------
__global__ void __launch_bounds__(256, 3) main_kernel(
    const int* __restrict__ ids_en, const int* __restrict__ ids_fr,
    const float* __restrict__ emb, float* __restrict__ out) {
    extern __shared__ char smem[];
    const uint32_t sb = smem_u32(smem);
    int* tfr = (int*)(smem + OFF_TFR);
    int* ten = (int*)(smem + OFF_TEN);

    const int b = blockIdx.x;
    const int coff = blockIdx.y * kN;
    const int tid = threadIdx.x;

    if (tid < 64)       tfr[tid]      = ids_fr[b * 64 + tid];
    else if (tid < 128) ten[tid - 64] = ids_en[b * 64 + (tid - 64)];
    __syncthreads();

    // ---- Fill B (V^T split) tiles: task = (k-pair kp, 8-n block) ------------
    // k even from row tfr[2kp] (low bf16 half), k odd from tfr[2kp+1] (high).
    for (int t4 = tid; t4 < 512; t4 += 256) {
        int kp = t4 & 31, n0 = (t4 >> 5) * 8;
        const uint32_t* p0 = g_projs + (size_t)tfr[2 * kp] * kD + coff + n0;
        const uint32_t* p1 = g_projs + (size_t)tfr[2 * kp + 1] * kD + coff + n0;
        uint4 v0a = __ldg((const uint4*)p0), v0b = __ldg((const uint4*)(p0 + 4));
        uint4 v1a = __ldg((const uint4*)p1), v1b = __ldg((const uint4*)(p1 + 4));
        uint32_t v0[8] = {v0a.x, v0a.y, v0a.z, v0a.w, v0b.x, v0b.y, v0b.z, v0b.w};
        uint32_t v1[8] = {v1a.x, v1a.y, v1a.z, v1a.w, v1b.x, v1b.y, v1b.z, v1b.w};
#pragma unroll
        for (int i = 0; i < 8; i++) {
            uint32_t off = (uint32_t)((n0 + i) * BST + kp * 4);
            *(uint32_t*)(smem + OFF_BHI + off) = prmt(v0[i], v1[i], 0x7632);
            *(uint32_t*)(smem + OFF_BLO + off) = prmt(v0[i], v1[i], 0x5410);
        }
    }
    // ---- Fill A (S split) tiles: task = (kp, q); masked packed-gram gather --
    for (int t4 = tid; t4 < 2048; t4 += 256) {
        int kp = t4 & 31, q = t4 >> 5;
        int t0 = tfr[2 * kp], t1 = tfr[2 * kp + 1];
        const uint32_t* gr = g_grams + (size_t)tfr[q] * kV;
        uint32_t v0 = t0 ? __ldg(gr + t0) : 0u;
        uint32_t v1 = t1 ? __ldg(gr + t1) : 0u;
        uint32_t off = (uint32_t)(q * AST + kp * 4);
        *(uint32_t*)(smem + OFF_AHI + off) = prmt(v0, v1, 0x7632);
        *(uint32_t*)(smem + OFF_ALO + off) = prmt(v0, v1, 0x5410);
    }
    __syncthreads();

    // ---- MMA phase ----------------------------------------------------------
    const int lane = tid & 31, w = tid >> 5;
    const int q0 = (w & 3) * 16;
    const int nbase = (w >> 2) * 64;

    const int arow = q0 + (lane & 7) + (lane & 8);
    const uint32_t aksel = ((lane >> 4) & 1) * 16;
    const uint32_t aHiB = sb + OFF_AHI + (uint32_t)arow * AST + aksel;
    const uint32_t aLoB = aHiB + (OFF_ALO - OFF_AHI);

    const int bln = (lane & 7) + ((lane >> 4) << 3);   // row within nt-pair
    const uint32_t bksel = ((lane >> 3) & 1) * 16;
    const uint32_t bHiB = sb + OFF_BHI + (uint32_t)(nbase + bln) * BST + bksel;
    const uint32_t bLoB = bHiB + (OFF_BLO - OFF_BHI);

    float acc[8][4];
#pragma unroll
    for (int nt = 0; nt < 8; nt++)
#pragma unroll
        for (int i = 0; i < 4; i++) acc[nt][i] = 0.f;

#pragma unroll
    for (int kk = 0; kk < 4; kk++) {
        uint32_t ah[4], al[4];
        ldsm4(ah, aHiB + kk * 32);
        ldsm4(al, aLoB + kk * 32);
#pragma unroll
        for (int p = 0; p < 4; p++) {
            uint32_t bh[4], bl[4];
            ldsm4(bh, bHiB + (uint32_t)(p * 16 * BST) + kk * 32);
            ldsm4(bl, bLoB + (uint32_t)(p * 16 * BST) + kk * 32);
            mma_bf16(acc[2 * p],     ah, bh);
            mma_bf16(acc[2 * p],     ah, bl);
            mma_bf16(acc[2 * p],     al, bh);
            mma_bf16(acc[2 * p + 1], ah, bh + 2);
            mma_bf16(acc[2 * p + 1], ah, bl + 2);
            mma_bf16(acc[2 * p + 1], al, bh + 2);
        }
    }

    // ---- Epilogue -----------------------------------------------------------
    const int row0 = q0 + (lane >> 2);
    const int row1 = row0 + 8;
    const int cl = 2 * (lane & 3);
    const float* e0 = emb + (size_t)ten[row0] * kD + coff + nbase + cl;
    const float* e1 = emb + (size_t)ten[row1] * kD + coff + nbase + cl;
    float* o0 = out + ((size_t)b * 64 + row0) * kD + coff + nbase + cl;
    float* o1 = out + ((size_t)b * 64 + row1) * kD + coff + nbase + cl;
#pragma unroll
    for (int nt = 0; nt < 8; nt++) {
        float2 g0 = __ldg((const float2*)(e0 + nt * 8));
        float2 g1 = __ldg((const float2*)(e1 + nt * 8));
        *(float2*)(o0 + nt * 8) = make_float2(acc[nt][0] + g0.x, acc[nt][1] + g0.y);
        *(float2*)(o1 + nt * 8) = make_float2(acc[nt][2] + g1.x, acc[nt][3] + g1.y);
    }
}

// ---------------------------------------------------------------------------
extern "C" void kernel_launch(void* const* d_in, const int* in_sizes, int n_in,
                              void* d_out, int out_size) {
    (void)in_sizes; (void)n_in; (void)out_size;
    const int* ids_en = (const int*)d_in[0];
    const int* ids_fr = (const int*)d_in[1];
    const float* emb  = (const float*)d_in[2];
    const float* Wq   = (const float*)d_in[3];
    float* out        = (float*)d_out;

    proj_kernel<<<dim3(38, 16), 256>>>(emb, Wq);
    gram_kernel<<<dim3(10, 10), 256>>>();
    cudaFuncSetAttribute(main_kernel, cudaFuncAttributeMaxDynamicSharedMemorySize,
                         SMEM_MAIN);
    main_kernel<<<dim3(kB, 4), 256, SMEM_MAIN>>>(ids_en, ids_fr, emb, out);
}